// round 1
// baseline (speedup 1.0000x reference)
#include <cuda_runtime.h>
#include <math.h>

#define NB    32       // batch
#define LSEQ  512      // sequence length
#define HID   1024     // hidden
#define G4    4096     // 4*HID (gates)
#define NCTA  128      // persistent CTAs (all-resident: 1/SM, 128 <= 148 SMs)
#define NTHR  256

// ---------------- persistent device scratch (allocation-free) ----------------
__device__ __align__(16) float g_x0[(size_t)NB * LSEQ * HID];     // embedding out
__device__ __align__(16) float g_x1[(size_t)NB * LSEQ * HID];     // layer-0 out
__device__ __align__(16) float g_P [(size_t)LSEQ * NB * G4];      // input-gate precompute [t][n][4096]
__device__ __align__(16) float g_h [2 * NB * HID];                // double-buffered hidden state
__device__ __align__(16) float g_c [NB * HID];                    // cell state
__device__ unsigned g_bar[32];                                    // grid barrier counter (padded line)

// ---------------- embedding gather: x0[n][t][:] = emb[tokens[n][t]] ----------------
__global__ void embed_kernel(const int* __restrict__ tokens, const float* __restrict__ emb)
{
    int idx = blockIdx.x;                       // idx = n*LSEQ + t
    int tok = tokens[idx];
    const float4* src = (const float4*)(emb + (size_t)tok * HID);
    float4* dst = (float4*)(g_x0 + (size_t)idx * HID);
    dst[threadIdx.x] = src[threadIdx.x];        // 256 threads * float4 = 1024 floats
}

// ---------------- input GEMM: P[m][j] = sum_k X[m][k] * Wx[j][k] + b[j] ----------------
// m = t*32 + n  (X row lives at (n*LSEQ + t)*HID), Wx[j][k] = Wm[j*2048 + 1024 + k]
__global__ void gemm_p_kernel(int src_sel, const float* __restrict__ Wl, const float* __restrict__ bl)
{
    const float* X = src_sel ? g_x1 : g_x0;
    __shared__ float As[64][17];
    __shared__ float Bs[64][17];

    int tid = threadIdx.x;
    int jb = blockIdx.x * 64;                   // output column block (j)
    int mb = blockIdx.y * 64;                   // output row block (m)

    int lm = tid >> 2;                          // 0..63
    int lk = (tid & 3) * 4;                     // 0,4,8,12

    int mg = mb + lm;
    const float* arow = X  + ((size_t)(mg & 31) * LSEQ + (mg >> 5)) * HID;
    const float* brow = Wl + (size_t)(jb + lm) * 2048 + 1024;

    int ty = tid >> 4, tx = tid & 15;
    float acc[4][4] = {};

    for (int k0 = 0; k0 < HID; k0 += 16) {
        __syncthreads();
        float4 av = *(const float4*)(arow + k0 + lk);
        float4 bv = *(const float4*)(brow + k0 + lk);
        As[lm][lk+0] = av.x; As[lm][lk+1] = av.y; As[lm][lk+2] = av.z; As[lm][lk+3] = av.w;
        Bs[lm][lk+0] = bv.x; Bs[lm][lk+1] = bv.y; Bs[lm][lk+2] = bv.z; Bs[lm][lk+3] = bv.w;
        __syncthreads();
        #pragma unroll
        for (int kk = 0; kk < 16; kk++) {
            float a[4], b[4];
            #pragma unroll
            for (int i = 0; i < 4; i++) { a[i] = As[ty*4+i][kk]; b[i] = Bs[tx*4+i][kk]; }
            #pragma unroll
            for (int i = 0; i < 4; i++)
                #pragma unroll
                for (int j = 0; j < 4; j++)
                    acc[i][j] += a[i] * b[j];
        }
    }

    #pragma unroll
    for (int i = 0; i < 4; i++) {
        int m = mb + ty*4 + i;
        float* prow = g_P + (size_t)m * G4 + jb;
        #pragma unroll
        for (int j = 0; j < 4; j++)
            prow[tx*4+j] = acc[i][j] + bl[jb + tx*4 + j];
    }
}

// ---------------- per-layer state reset (graph-replay determinism) ----------------
__global__ void reset_kernel()
{
    int i = blockIdx.x * blockDim.x + threadIdx.x;
    int stride = gridDim.x * blockDim.x;
    for (int k = i; k < 2 * NB * HID; k += stride) g_h[k] = 0.f;
    for (int k = i; k < NB * HID;     k += stride) g_c[k] = 0.f;
    if (i < 32) g_bar[i] = 0u;
}

// ---------------- persistent recurrent kernel ----------------
// CTA b owns h-indices j0=b*8..b*8+7 -> 32 Wm rows (gate g, local lh): row = g*1024 + j0 + lh.
// Wh slice (cols 0..1023) lives in smem (32 rows x 256 float4 = 128 KB), stationary across all 512 steps.
// Per step: g[row][n] = sum_k Ws[row][k] * h_prev[n][k], then gates+cell update for 8 h x 32 n.
__global__ void __launch_bounds__(NTHR, 1)
lstm_rec_kernel(const float* __restrict__ Wl, int out_sel, float* __restrict__ out_ext)
{
    extern __shared__ float4 Ws[];              // [32][256] float4
    __shared__ float gsm[32][33];               // reduced gate pre-activations [row][n]

    float* Y = out_sel ? out_ext : g_x1;

    int tid = threadIdx.x;
    int j0  = blockIdx.x * 8;

    // load stationary weight slice
    for (int idx = tid; idx < 32 * 256; idx += NTHR) {
        int r  = idx >> 8;                      // 0..31 local row
        int k4 = idx & 255;                     // float4 index along K
        int grow = (r >> 3) * HID + j0 + (r & 7);
        Ws[idx] = *(const float4*)(Wl + (size_t)grow * 2048 + k4 * 4);
    }
    __syncthreads();

    // compute-phase mapping: tid = (rb*8 + nb)*8 + kp
    int kp   = tid & 7;                         // k-split (interleaved)
    int tile = tid >> 3;                        // 0..31
    int nb   = tile & 7;                        // batch block: n = nb*4 + i
    int rb   = tile >> 3;                       // row block:   r = rb*8 + rr

    // gate-phase mapping
    int gp_n  = tid >> 3;                       // 0..31
    int gp_lh = tid & 7;                        // 0..7

    for (int t = 0; t < LSEQ; t++) {
        if (t) {
            __syncthreads();
            if (tid == 0) {
                __threadfence();
                atomicAdd(&g_bar[0], 1u);
                unsigned target = (unsigned)t * NCTA;
                while (*(volatile unsigned*)&g_bar[0] < target) __nanosleep(40);
                __threadfence();
            }
            __syncthreads();
        }

        const float4* hbuf = (const float4*)(g_h + (t & 1) * (NB * HID));

        float acc[8][4];
        #pragma unroll
        for (int r = 0; r < 8; r++)
            #pragma unroll
            for (int i = 0; i < 4; i++) acc[r][i] = 0.f;

        for (int kk = 0; kk < 32; kk++) {
            int k4 = kk * 8 + kp;               // interleaved k-split: conflict-free LDS
            float4 h4[4];
            #pragma unroll
            for (int i = 0; i < 4; i++)
                h4[i] = hbuf[(nb * 4 + i) * 256 + k4];
            #pragma unroll
            for (int r = 0; r < 8; r++) {
                float4 w = Ws[(rb * 8 + r) * 256 + k4];
                #pragma unroll
                for (int i = 0; i < 4; i++) {
                    acc[r][i] += w.x * h4[i].x;
                    acc[r][i] += w.y * h4[i].y;
                    acc[r][i] += w.z * h4[i].z;
                    acc[r][i] += w.w * h4[i].w;
                }
            }
        }

        // reduce over the 8 k-split lanes (consecutive lanes)
        #pragma unroll
        for (int r = 0; r < 8; r++)
            #pragma unroll
            for (int i = 0; i < 4; i++) {
                float v = acc[r][i];
                v += __shfl_down_sync(0xffffffffu, v, 4, 8);
                v += __shfl_down_sync(0xffffffffu, v, 2, 8);
                v += __shfl_down_sync(0xffffffffu, v, 1, 8);
                acc[r][i] = v;
            }
        if (kp == 0) {
            #pragma unroll
            for (int r = 0; r < 8; r++)
                #pragma unroll
                for (int i = 0; i < 4; i++)
                    gsm[rb * 8 + r][nb * 4 + i] = acc[r][i];
        }
        __syncthreads();

        // gates + cell update: 256 threads <-> 32 n x 8 local-h
        {
            int n = gp_n, lh = gp_lh;
            int j = j0 + lh;
            const float* Pb = g_P + ((size_t)t * NB + n) * G4;
            float xf = gsm[      lh][n] + Pb[         j];
            float xi = gsm[ 8 + lh][n] + Pb[1024 + j];
            float xo = gsm[16 + lh][n] + Pb[2048 + j];
            float xc = gsm[24 + lh][n] + Pb[3072 + j];   // raw candidate (reference has no tanh here)

            float f  = 1.f / (1.f + expf(-xf));
            float ii = 1.f / (1.f + expf(-xi));
            float o  = 1.f / (1.f + expf(-xo));

            int ci = n * HID + j;
            float c = f * g_c[ci] + ii * xc;
            g_c[ci] = c;
            float h = o * tanhf(c);
            g_h[((t + 1) & 1) * (NB * HID) + ci] = h;    // write buffer for step t+1
            Y[((size_t)n * LSEQ + t) * HID + j] = h;
        }
        // next-iteration barrier's __syncthreads protects gsm reuse
    }
}

// ---------------- launch ----------------
extern "C" void kernel_launch(void* const* d_in, const int* in_sizes, int n_in,
                              void* d_out, int out_size)
{
    const int*   tokens = (const int*)  d_in[0];
    const float* emb    = (const float*)d_in[1];
    const float* W      = (const float*)d_in[2];
    const float* b      = (const float*)d_in[3];
    float* out = (float*)d_out;

    cudaFuncSetAttribute(lstm_rec_kernel, cudaFuncAttributeMaxDynamicSharedMemorySize, 131072);

    const size_t WSTRIDE = (size_t)4 * HID * 2 * HID;    // 8388608 floats per layer
    const size_t BSTRIDE = (size_t)4 * HID;              // 4096 floats per layer

    embed_kernel<<<NB * LSEQ, 256>>>(tokens, emb);

    dim3 gg(G4 / 64, (NB * LSEQ) / 64);

    // layer 0
    gemm_p_kernel<<<gg, 256>>>(0, W, b);
    reset_kernel<<<64, 256>>>();
    lstm_rec_kernel<<<NCTA, NTHR, 131072>>>(W, 0, nullptr);

    // layer 1
    gemm_p_kernel<<<gg, 256>>>(1, W + WSTRIDE, b + BSTRIDE);
    reset_kernel<<<64, 256>>>();
    lstm_rec_kernel<<<NCTA, NTHR, 131072>>>(W + WSTRIDE, 1, out);
}

// round 5
// speedup vs baseline: 1.2580x; 1.2580x over previous
#include <cuda_runtime.h>
#include <math.h>

#define NB    32       // batch
#define LSEQ  512      // sequence length
#define HID   1024     // hidden
#define G4    4096     // 4*HID (gates)
#define NCTA  128      // persistent CTAs (1/SM, all-resident)
#define NTHR  256

// ---------------- f32x2 packed-FMA helpers (sm_100+) ----------------
__device__ __forceinline__ unsigned long long pk2(float lo, float hi) {
    unsigned long long r;
    asm("mov.b64 %0, {%1, %2};" : "=l"(r) : "r"(__float_as_uint(lo)), "r"(__float_as_uint(hi)));
    return r;
}
__device__ __forceinline__ void fma2(unsigned long long& d, unsigned long long a, unsigned long long b) {
    asm("fma.rn.f32x2 %0, %1, %2, %0;" : "+l"(d) : "l"(a), "l"(b));
}
__device__ __forceinline__ float red2(unsigned long long v) {
    unsigned lo, hi;
    asm("mov.b64 {%0, %1}, %2;" : "=r"(lo), "=r"(hi) : "l"(v));
    return __uint_as_float(lo) + __uint_as_float(hi);
}

// ---------------- persistent device scratch (allocation-free) ----------------
__device__ __align__(16) float g_x0[(size_t)NB * LSEQ * HID];
__device__ __align__(16) float g_x1[(size_t)NB * LSEQ * HID];
__device__ __align__(16) float g_P [(size_t)LSEQ * NB * G4];      // [t][n][4096]
__device__ __align__(16) float g_h [2 * NB * HID];
__device__ __align__(16) float g_c [NB * HID];
__device__ unsigned g_bar[32];

// ---------------- embedding gather ----------------
__global__ void embed_kernel(const int* __restrict__ tokens, const float* __restrict__ emb)
{
    int idx = blockIdx.x;                       // n*LSEQ + t
    int tok = tokens[idx];
    const float4* src = (const float4*)(emb + (size_t)tok * HID);
    float4* dst = (float4*)(g_x0 + (size_t)idx * HID);
    dst[threadIdx.x] = src[threadIdx.x];
}

// ---------------- input GEMM (f32x2): P[m][j] = X[m][:] . Wx[j][:] + b[j] ----------------
// 128x64 tile, 256 threads, thread = 8m x 4j, k-paired accumulators.
// m = t*32 + n  (X row at (n*LSEQ + t)*HID);  Wx[j][k] = Wl[j*2048 + 1024 + k]
__global__ void __launch_bounds__(NTHR) gemm_p_kernel(int src_sel, const float* __restrict__ Wl, const float* __restrict__ bl)
{
    const float* X = src_sel ? g_x1 : g_x0;
    __shared__ float2 Asp[8][128];              // [kpair][m] within 16-k slab
    __shared__ float2 Bsp[8][64];               // [kpair][j]

    int tid = threadIdx.x;
    int jb = blockIdx.x * 64;
    int mb = blockIdx.y * 128;

    int ty = tid >> 4;                          // 0..15 -> m base ty*8
    int tx = tid & 15;                          // 0..15 -> j base tx*4

    int lr  = tid >> 2;                         // fill row 0..63
    int lk  = (tid & 3) * 4;                    // fill k offset 0,4,8,12
    int lk2 = (tid & 3) * 2;                    // k-pair index

    unsigned long long acc2[8][4];
    #pragma unroll
    for (int i = 0; i < 8; i++)
        #pragma unroll
        for (int j = 0; j < 4; j++) acc2[i][j] = 0ull;

    for (int k0 = 0; k0 < HID; k0 += 16) {
        __syncthreads();
        // fill A: two passes of 64 rows
        #pragma unroll
        for (int p = 0; p < 2; p++) {
            int mg = mb + lr + p * 64;
            const float* arow = X + ((size_t)(mg & 31) * LSEQ + (mg >> 5)) * HID;
            float4 av = *(const float4*)(arow + k0 + lk);
            Asp[lk2    ][lr + p * 64] = make_float2(av.x, av.y);
            Asp[lk2 + 1][lr + p * 64] = make_float2(av.z, av.w);
        }
        // fill B: 64 rows
        {
            const float* brow = Wl + (size_t)(jb + lr) * 2048 + 1024;
            float4 bv = *(const float4*)(brow + k0 + lk);
            Bsp[lk2    ][lr] = make_float2(bv.x, bv.y);
            Bsp[lk2 + 1][lr] = make_float2(bv.z, bv.w);
        }
        __syncthreads();

        #pragma unroll
        for (int kk2 = 0; kk2 < 8; kk2++) {
            float4 a0 = *(const float4*)&Asp[kk2][ty * 8 + 0];
            float4 a1 = *(const float4*)&Asp[kk2][ty * 8 + 2];
            float4 a2 = *(const float4*)&Asp[kk2][ty * 8 + 4];
            float4 a3 = *(const float4*)&Asp[kk2][ty * 8 + 6];
            float4 b0 = *(const float4*)&Bsp[kk2][tx * 4 + 0];
            float4 b1 = *(const float4*)&Bsp[kk2][tx * 4 + 2];
            unsigned long long A2[8], B2[4];
            A2[0] = pk2(a0.x, a0.y); A2[1] = pk2(a0.z, a0.w);
            A2[2] = pk2(a1.x, a1.y); A2[3] = pk2(a1.z, a1.w);
            A2[4] = pk2(a2.x, a2.y); A2[5] = pk2(a2.z, a2.w);
            A2[6] = pk2(a3.x, a3.y); A2[7] = pk2(a3.z, a3.w);
            B2[0] = pk2(b0.x, b0.y); B2[1] = pk2(b0.z, b0.w);
            B2[2] = pk2(b1.x, b1.y); B2[3] = pk2(b1.z, b1.w);
            #pragma unroll
            for (int i = 0; i < 8; i++)
                #pragma unroll
                for (int j = 0; j < 4; j++)
                    fma2(acc2[i][j], A2[i], B2[j]);
        }
    }

    float4 bias = *(const float4*)(bl + jb + tx * 4);
    #pragma unroll
    for (int i = 0; i < 8; i++) {
        int m = mb + ty * 8 + i;
        float4 st;
        st.x = red2(acc2[i][0]) + bias.x;
        st.y = red2(acc2[i][1]) + bias.y;
        st.z = red2(acc2[i][2]) + bias.z;
        st.w = red2(acc2[i][3]) + bias.w;
        *(float4*)(g_P + (size_t)m * G4 + jb + tx * 4) = st;
    }
}

// ---------------- per-layer state reset ----------------
__global__ void reset_kernel()
{
    int i = blockIdx.x * blockDim.x + threadIdx.x;
    int stride = gridDim.x * blockDim.x;
    for (int k = i; k < 2 * NB * HID; k += stride) g_h[k] = 0.f;
    for (int k = i; k < NB * HID;     k += stride) g_c[k] = 0.f;
    if (i < 32) g_bar[i] = 0u;
}

// ---------------- persistent recurrent kernel (f32x2 + smem-staged h) ----------------
// CTA owns h-indices j0..j0+7 -> 32 Wm rows stationary in smem (128 KB).
// h (32 x 1024) staged through smem in 4 chunks of 256 k (32 KB).
__global__ void __launch_bounds__(NTHR, 1)
lstm_rec_kernel(const float* __restrict__ Wl, int out_sel, float* __restrict__ out_ext)
{
    extern __shared__ float4 sm4[];
    float4* Ws = sm4;                           // [32][256] float4  (128 KB)
    float4* Hs = sm4 + 32 * 256;                // [32][64]  float4  (32 KB chunk)
    __shared__ float gsm[32][33];

    float* Y = out_sel ? out_ext : g_x1;
    int tid = threadIdx.x;
    int j0  = blockIdx.x * 8;

    // stationary weight slice
    for (int idx = tid; idx < 32 * 256; idx += NTHR) {
        int r  = idx >> 8;
        int k4 = idx & 255;
        int grow = (r >> 3) * HID + j0 + (r & 7);
        Ws[idx] = *(const float4*)(Wl + (size_t)grow * 2048 + k4 * 4);
    }
    __syncthreads();

    // compute mapping: tid = (rb*8 + nb)*8 + kp
    int kp   = tid & 7;
    int tile = tid >> 3;
    int nb   = tile & 7;
    int rb   = tile >> 3;

    int gp_n  = tid >> 3;
    int gp_lh = tid & 7;

    for (int t = 0; t < LSEQ; t++) {
        if (t) {
            __syncthreads();
            if (tid == 0) {
                __threadfence();
                atomicAdd(&g_bar[0], 1u);
                unsigned target = (unsigned)t * NCTA;
                while (*(volatile unsigned*)&g_bar[0] < target) __nanosleep(40);
                __threadfence();
            }
            __syncthreads();
        }

        const float4* hbuf = (const float4*)(g_h + (t & 1) * (NB * HID));

        unsigned long long acc2[8][4];
        #pragma unroll
        for (int r = 0; r < 8; r++)
            #pragma unroll
            for (int i = 0; i < 4; i++) acc2[r][i] = 0ull;

        for (int c = 0; c < 4; c++) {
            __syncthreads();                    // previous chunk fully consumed
            #pragma unroll
            for (int u = 0; u < 8; u++) {       // stage 2048 float4 (coalesced)
                int idx = u * NTHR + tid;
                int n = idx >> 6, k4l = idx & 63;
                Hs[idx] = hbuf[n * 256 + c * 64 + k4l];
            }
            __syncthreads();

            #pragma unroll
            for (int kk = 0; kk < 8; kk++) {
                int k4l = kk * 8 + kp;
                float4 h4[4];
                unsigned long long hlo[4], hhi[4];
                #pragma unroll
                for (int i = 0; i < 4; i++) {
                    h4[i] = Hs[(nb * 4 + i) * 64 + k4l];
                    hlo[i] = pk2(h4[i].x, h4[i].y);
                    hhi[i] = pk2(h4[i].z, h4[i].w);
                }
                #pragma unroll
                for (int r = 0; r < 8; r++) {
                    float4 w = Ws[(rb * 8 + r) * 256 + c * 64 + k4l];
                    unsigned long long wlo = pk2(w.x, w.y);
                    unsigned long long whi = pk2(w.z, w.w);
                    #pragma unroll
                    for (int i = 0; i < 4; i++) {
                        fma2(acc2[r][i], wlo, hlo[i]);
                        fma2(acc2[r][i], whi, hhi[i]);
                    }
                }
            }
        }

        // reduce k-halves then the 8 k-split lanes
        #pragma unroll
        for (int r = 0; r < 8; r++)
            #pragma unroll
            for (int i = 0; i < 4; i++) {
                float v = red2(acc2[r][i]);
                v += __shfl_down_sync(0xffffffffu, v, 4, 8);
                v += __shfl_down_sync(0xffffffffu, v, 2, 8);
                v += __shfl_down_sync(0xffffffffu, v, 1, 8);
                if (kp == 0) gsm[rb * 8 + r][nb * 4 + i] = v;
            }
        __syncthreads();

        // gates + cell update: 256 threads <-> 32 n x 8 local-h
        {
            int n = gp_n, lh = gp_lh;
            int j = j0 + lh;
            const float* Pb = g_P + ((size_t)t * NB + n) * G4;
            float xf = gsm[      lh][n] + Pb[       j];
            float xi = gsm[ 8 + lh][n] + Pb[1024 + j];
            float xo = gsm[16 + lh][n] + Pb[2048 + j];
            float xc = gsm[24 + lh][n] + Pb[3072 + j];

            float f  = 1.f / (1.f + __expf(-xf));
            float ii = 1.f / (1.f + __expf(-xi));
            float o  = 1.f / (1.f + __expf(-xo));

            int ci = n * HID + j;
            float cc = f * g_c[ci] + ii * xc;
            g_c[ci] = cc;
            float h = o * tanhf(cc);
            g_h[((t + 1) & 1) * (NB * HID) + ci] = h;
            Y[((size_t)n * LSEQ + t) * HID + j] = h;
        }
    }
}

// ---------------- launch ----------------
extern "C" void kernel_launch(void* const* d_in, const int* in_sizes, int n_in,
                              void* d_out, int out_size)
{
    const int*   tokens = (const int*)  d_in[0];
    const float* emb    = (const float*)d_in[1];
    const float* W      = (const float*)d_in[2];
    const float* b      = (const float*)d_in[3];
    float* out = (float*)d_out;

    const int REC_SMEM = 32 * 256 * 16 + 32 * 64 * 16;   // 160 KB dynamic
    cudaFuncSetAttribute(lstm_rec_kernel, cudaFuncAttributeMaxDynamicSharedMemorySize, REC_SMEM);

    const size_t WSTRIDE = (size_t)4 * HID * 2 * HID;
    const size_t BSTRIDE = (size_t)4 * HID;

    embed_kernel<<<NB * LSEQ, 256>>>(tokens, emb);

    dim3 gg(G4 / 64, (NB * LSEQ) / 128);

    // layer 0
    gemm_p_kernel<<<gg, NTHR>>>(0, W, b);
    reset_kernel<<<64, 256>>>();
    lstm_rec_kernel<<<NCTA, NTHR, REC_SMEM>>>(W, 0, nullptr);

    // layer 1
    gemm_p_kernel<<<gg, NTHR>>>(1, W + WSTRIDE, b + BSTRIDE);
    reset_kernel<<<64, 256>>>();
    lstm_rec_kernel<<<NCTA, NTHR, REC_SMEM>>>(W + WSTRIDE, 1, out);
}

// round 17
// speedup vs baseline: 1.2895x; 1.0250x over previous
#include <cuda_runtime.h>
#include <math.h>

#define NB    32       // batch
#define LSEQ  512      // sequence length
#define HID   1024     // hidden
#define G4    4096     // 4*HID (gates)
#define NCTA  128      // persistent CTAs (1/SM, all-resident)
#define NTHR  256

// ---------------- f32x2 packed-FMA helpers (sm_100+) ----------------
__device__ __forceinline__ unsigned long long pk2(float lo, float hi) {
    unsigned long long r;
    asm("mov.b64 %0, {%1, %2};" : "=l"(r) : "r"(__float_as_uint(lo)), "r"(__float_as_uint(hi)));
    return r;
}
__device__ __forceinline__ void fma2(unsigned long long& d, unsigned long long a, unsigned long long b) {
    asm("fma.rn.f32x2 %0, %1, %2, %0;" : "+l"(d) : "l"(a), "l"(b));
}
__device__ __forceinline__ float red2(unsigned long long v) {
    unsigned lo, hi;
    asm("mov.b64 {%0, %1}, %2;" : "=r"(lo), "=r"(hi) : "l"(v));
    return __uint_as_float(lo) + __uint_as_float(hi);
}

// ---------------- persistent device scratch (allocation-free) ----------------
__device__ __align__(16) float g_x0[(size_t)NB * LSEQ * HID];
__device__ __align__(16) float g_x1[(size_t)NB * LSEQ * HID];
__device__ __align__(16) float g_P [(size_t)LSEQ * NB * G4];      // [t][n][4096]
__device__ __align__(16) float g_h [2 * NB * HID];
__device__ __align__(16) float g_c [NB * HID];
__device__ unsigned g_bar[32];

// ---------------- embedding gather ----------------
__global__ void embed_kernel(const int* __restrict__ tokens, const float* __restrict__ emb)
{
    int idx = blockIdx.x;                       // n*LSEQ + t
    int tok = tokens[idx];
    const float4* src = (const float4*)(emb + (size_t)tok * HID);
    float4* dst = (float4*)(g_x0 + (size_t)idx * HID);
    dst[threadIdx.x] = src[threadIdx.x];
}

// ---------------- input GEMM (f32x2): P[m][j] = X[m][:] . Wx[j][:] + b[j] ----------------
// PROVEN round-5 version, byte-identical.
__global__ void __launch_bounds__(NTHR) gemm_p_kernel(int src_sel, const float* __restrict__ Wl, const float* __restrict__ bl)
{
    const float* X = src_sel ? g_x1 : g_x0;
    __shared__ float2 Asp[8][128];
    __shared__ float2 Bsp[8][64];

    int tid = threadIdx.x;
    int jb = blockIdx.x * 64;
    int mb = blockIdx.y * 128;

    int ty = tid >> 4;
    int tx = tid & 15;

    int lr  = tid >> 2;
    int lk  = (tid & 3) * 4;
    int lk2 = (tid & 3) * 2;

    unsigned long long acc2[8][4];
    #pragma unroll
    for (int i = 0; i < 8; i++)
        #pragma unroll
        for (int j = 0; j < 4; j++) acc2[i][j] = 0ull;

    for (int k0 = 0; k0 < HID; k0 += 16) {
        __syncthreads();
        #pragma unroll
        for (int p = 0; p < 2; p++) {
            int mg = mb + lr + p * 64;
            const float* arow = X + ((size_t)(mg & 31) * LSEQ + (mg >> 5)) * HID;
            float4 av = *(const float4*)(arow + k0 + lk);
            Asp[lk2    ][lr + p * 64] = make_float2(av.x, av.y);
            Asp[lk2 + 1][lr + p * 64] = make_float2(av.z, av.w);
        }
        {
            const float* brow = Wl + (size_t)(jb + lr) * 2048 + 1024;
            float4 bv = *(const float4*)(brow + k0 + lk);
            Bsp[lk2    ][lr] = make_float2(bv.x, bv.y);
            Bsp[lk2 + 1][lr] = make_float2(bv.z, bv.w);
        }
        __syncthreads();

        #pragma unroll
        for (int kk2 = 0; kk2 < 8; kk2++) {
            float4 a0 = *(const float4*)&Asp[kk2][ty * 8 + 0];
            float4 a1 = *(const float4*)&Asp[kk2][ty * 8 + 2];
            float4 a2 = *(const float4*)&Asp[kk2][ty * 8 + 4];
            float4 a3 = *(const float4*)&Asp[kk2][ty * 8 + 6];
            float4 b0 = *(const float4*)&Bsp[kk2][tx * 4 + 0];
            float4 b1 = *(const float4*)&Bsp[kk2][tx * 4 + 2];
            unsigned long long A2[8], B2[4];
            A2[0] = pk2(a0.x, a0.y); A2[1] = pk2(a0.z, a0.w);
            A2[2] = pk2(a1.x, a1.y); A2[3] = pk2(a1.z, a1.w);
            A2[4] = pk2(a2.x, a2.y); A2[5] = pk2(a2.z, a2.w);
            A2[6] = pk2(a3.x, a3.y); A2[7] = pk2(a3.z, a3.w);
            B2[0] = pk2(b0.x, b0.y); B2[1] = pk2(b0.z, b0.w);
            B2[2] = pk2(b1.x, b1.y); B2[3] = pk2(b1.z, b1.w);
            #pragma unroll
            for (int i = 0; i < 8; i++)
                #pragma unroll
                for (int j = 0; j < 4; j++)
                    fma2(acc2[i][j], A2[i], B2[j]);
        }
    }

    float4 bias = *(const float4*)(bl + jb + tx * 4);
    #pragma unroll
    for (int i = 0; i < 8; i++) {
        int m = mb + ty * 8 + i;
        float4 st;
        st.x = red2(acc2[i][0]) + bias.x;
        st.y = red2(acc2[i][1]) + bias.y;
        st.z = red2(acc2[i][2]) + bias.z;
        st.w = red2(acc2[i][3]) + bias.w;
        *(float4*)(g_P + (size_t)m * G4 + jb + tx * 4) = st;
    }
}

// ---------------- per-layer state reset ----------------
__global__ void reset_kernel()
{
    int i = blockIdx.x * blockDim.x + threadIdx.x;
    int stride = gridDim.x * blockDim.x;
    for (int k = i; k < 2 * NB * HID; k += stride) g_h[k] = 0.f;
    for (int k = i; k < NB * HID;     k += stride) g_c[k] = 0.f;
    if (i < 32) g_bar[i] = 0u;
}

// ---------------- persistent recurrent kernel ----------------
// Round-5 algorithm + pipelining: double-buffered h staging (1 sync/chunk),
// P gate-values prefetched at step start, hot-spin barrier.
__global__ void __launch_bounds__(NTHR, 1)
lstm_rec_kernel(const float* __restrict__ Wl, int out_sel, float* __restrict__ out_ext)
{
    extern __shared__ float4 sm4[];
    float4* Ws = sm4;                           // [32][256] float4  (128 KB)
    float4* Hs = sm4 + 32 * 256;                // 2 x [32][64] float4 (2 x 32 KB)
    __shared__ float gsm[32][33];

    float* Y = out_sel ? out_ext : g_x1;
    int tid = threadIdx.x;
    int j0  = blockIdx.x * 8;

    // stationary weight slice
    for (int idx = tid; idx < 32 * 256; idx += NTHR) {
        int r  = idx >> 8;
        int k4 = idx & 255;
        int grow = (r >> 3) * HID + j0 + (r & 7);
        Ws[idx] = *(const float4*)(Wl + (size_t)grow * 2048 + k4 * 4);
    }
    __syncthreads();

    // compute mapping: tid = (rb*8 + nb)*8 + kp
    int kp   = tid & 7;
    int tile = tid >> 3;
    int nb   = tile & 7;
    int rb   = tile >> 3;

    int gp_n  = tid >> 3;
    int gp_lh = tid & 7;
    int gp_j  = j0 + gp_lh;

    for (int t = 0; t < LSEQ; t++) {
        if (t) {
            __syncthreads();
            if (tid == 0) {
                __threadfence();
                atomicAdd(&g_bar[0], 1u);
                unsigned target = (unsigned)t * NCTA;
                while (*(volatile unsigned*)&g_bar[0] < target) { }
                __threadfence();
            }
            __syncthreads();
        }

        const float4* hbuf = (const float4*)(g_h + (t & 1) * (NB * HID));
        const float* Pb = g_P + ((size_t)t * NB + gp_n) * G4;

        // prefetch this step's P gate values (LDG hidden behind matvec)
        float pf = Pb[       gp_j];
        float pi = Pb[1024 + gp_j];
        float po = Pb[2048 + gp_j];
        float pc = Pb[3072 + gp_j];

        unsigned long long acc2[8][4];
        #pragma unroll
        for (int r = 0; r < 8; r++)
            #pragma unroll
            for (int i = 0; i < 4; i++) acc2[r][i] = 0ull;

        // stage chunk 0
        #pragma unroll
        for (int u = 0; u < 8; u++) {
            int idx = u * NTHR + tid;
            int n = idx >> 6, k4l = idx & 63;
            Hs[idx] = hbuf[n * 256 + k4l];
        }
        __syncthreads();

        for (int c = 0; c < 4; c++) {
            // prefetch chunk c+1 into the other buffer (overlaps compute below)
            if (c < 3) {
                float4* Hn = Hs + ((c + 1) & 1) * 2048;
                #pragma unroll
                for (int u = 0; u < 8; u++) {
                    int idx = u * NTHR + tid;
                    int n = idx >> 6, k4l = idx & 63;
                    Hn[idx] = hbuf[n * 256 + (c + 1) * 64 + k4l];
                }
            }

            const float4* Hc = Hs + (c & 1) * 2048;
            #pragma unroll
            for (int kk = 0; kk < 8; kk++) {
                int k4l = kk * 8 + kp;
                float4 h4[4];
                unsigned long long hlo[4], hhi[4];
                #pragma unroll
                for (int i = 0; i < 4; i++) {
                    h4[i] = Hc[(nb * 4 + i) * 64 + k4l];
                    hlo[i] = pk2(h4[i].x, h4[i].y);
                    hhi[i] = pk2(h4[i].z, h4[i].w);
                }
                #pragma unroll
                for (int r = 0; r < 8; r++) {
                    float4 w = Ws[(rb * 8 + r) * 256 + c * 64 + k4l];
                    unsigned long long wlo = pk2(w.x, w.y);
                    unsigned long long whi = pk2(w.z, w.w);
                    #pragma unroll
                    for (int i = 0; i < 4; i++) {
                        fma2(acc2[r][i], wlo, hlo[i]);
                        fma2(acc2[r][i], whi, hhi[i]);
                    }
                }
            }
            __syncthreads();   // compute(c) done + fill(c+1) visible; buffer c&1 free for fill(c+2)
        }

        // reduce k-halves then the 8 k-split lanes
        #pragma unroll
        for (int r = 0; r < 8; r++)
            #pragma unroll
            for (int i = 0; i < 4; i++) {
                float v = red2(acc2[r][i]);
                v += __shfl_down_sync(0xffffffffu, v, 4, 8);
                v += __shfl_down_sync(0xffffffffu, v, 2, 8);
                v += __shfl_down_sync(0xffffffffu, v, 1, 8);
                if (kp == 0) gsm[rb * 8 + r][nb * 4 + i] = v;
            }
        __syncthreads();

        // gates + cell update: 256 threads <-> 32 n x 8 local-h
        {
            int n = gp_n, lh = gp_lh;
            float xf = gsm[      lh][n] + pf;
            float xi = gsm[ 8 + lh][n] + pi;
            float xo = gsm[16 + lh][n] + po;
            float xc = gsm[24 + lh][n] + pc;

            float f  = 1.f / (1.f + __expf(-xf));
            float ii = 1.f / (1.f + __expf(-xi));
            float o  = 1.f / (1.f + __expf(-xo));

            int ci = n * HID + gp_j;
            float cc = f * g_c[ci] + ii * xc;
            g_c[ci] = cc;
            float h = o * tanhf(cc);
            g_h[((t + 1) & 1) * (NB * HID) + ci] = h;
            Y[((size_t)n * LSEQ + t) * HID + gp_j] = h;
        }
    }
}

// ---------------- launch ----------------
extern "C" void kernel_launch(void* const* d_in, const int* in_sizes, int n_in,
                              void* d_out, int out_size)
{
    const int*   tokens = (const int*)  d_in[0];
    const float* emb    = (const float*)d_in[1];
    const float* W      = (const float*)d_in[2];
    const float* b      = (const float*)d_in[3];
    float* out = (float*)d_out;

    const int REC_SMEM = 32 * 256 * 16 + 2 * 32 * 64 * 16;   // 128KB + 64KB = 192 KB dynamic
    cudaFuncSetAttribute(lstm_rec_kernel, cudaFuncAttributeMaxDynamicSharedMemorySize, REC_SMEM);

    const size_t WSTRIDE = (size_t)4 * HID * 2 * HID;
    const size_t BSTRIDE = (size_t)4 * HID;

    embed_kernel<<<NB * LSEQ, 256>>>(tokens, emb);

    dim3 gg(G4 / 64, (NB * LSEQ) / 128);

    // layer 0
    gemm_p_kernel<<<gg, NTHR>>>(0, W, b);
    reset_kernel<<<64, 256>>>();
    lstm_rec_kernel<<<NCTA, NTHR, REC_SMEM>>>(W, 0, nullptr);

    // layer 1
    gemm_p_kernel<<<gg, NTHR>>>(1, W + WSTRIDE, b + BSTRIDE);
    reset_kernel<<<64, 256>>>();
    lstm_rec_kernel<<<NCTA, NTHR, REC_SMEM>>>(W + WSTRIDE, 1, out);
}